// round 1
// baseline (speedup 1.0000x reference)
#include <cuda_runtime.h>
#include <math.h>

#define Bq 2
#define Tt 1024
#define DM 512
#define Hh 8
#define DEP 64
#define NTOK (Bq*Tt)      // 2048
#define BH   (Bq*Hh)      // 16
#define NBHT (BH*Tt)      // 16384

// ---------------- scratch (device globals; no allocation) ----------------
__device__ float g_Q[NTOK*DM];
__device__ float g_K[NTOK*DM];
__device__ float g_V[NTOK*DM];
__device__ float g_Cb[NTOK*DM];
__device__ float g_S[(size_t)BH*Tt*Tt];   // 64 MB scores
__device__ float g_wphi[128];
__device__ float g_wtau[128];
__device__ float g_cphi[1];
__device__ float g_ctau[1];
__device__ float g_pq_phi[NBHT], g_pk_phi[NBHT];
__device__ float g_pq_ta [NBHT], g_pk_ta [NBHT];
__device__ float g_pq_tb [NBHT], g_pk_tb [NBHT];
__device__ float g_pq_tau[NBHT], g_pk_tau[NBHT];

// ---------------- 1. collapse the linear-linear per-pair MLPs ----------------
__global__ void combine_kernel(const float* __restrict__ Wpi, const float* __restrict__ bpi,
                               const float* __restrict__ Wpo, const float* __restrict__ bpo,
                               const float* __restrict__ Wti, const float* __restrict__ bti,
                               const float* __restrict__ Wto, const float* __restrict__ bto) {
    int i = threadIdx.x;  // 128 threads
    float s = 0.f;
    for (int m = 0; m < 512; m++) s += Wpi[i*512 + m] * Wpo[m];
    g_wphi[i] = s;
    float s2 = 0.f;
    for (int m = 0; m < 256; m++) s2 += Wti[i*256 + m] * Wto[m];
    g_wtau[i] = s2;
    if (i == 0) {
        float c = bpo[0];
        for (int m = 0; m < 512; m++) c += bpi[m] * Wpo[m];
        g_cphi[0] = c;
        float c2 = bto[0];
        for (int m = 0; m < 256; m++) c2 += bti[m] * Wto[m];
        g_ctau[0] = c2;
    }
}

// ---------------- 2. generic GEMM: C[M,N] = A[M,K] @ W[K,N] + bias ----------------
// 64x64 tile, BK=16, 256 threads, 4x4 per thread
__global__ void gemm_bias(const float* __restrict__ A, const float* __restrict__ W,
                          const float* __restrict__ bias, float* __restrict__ C,
                          int M, int N, int K) {
    __shared__ float As[16][65];
    __shared__ float Ws[16][65];
    const int tid = threadIdx.x;
    const int tx = tid & 15, ty = tid >> 4;
    const int m0 = blockIdx.y * 64, n0 = blockIdx.x * 64;
    float acc[4][4] = {};
    for (int k0 = 0; k0 < K; k0 += 16) {
        #pragma unroll
        for (int i = 0; i < 4; i++) {
            int e = tid + i*256;           // 0..1023
            int m = e >> 4, kk = e & 15;
            As[kk][m] = A[(size_t)(m0+m)*K + k0 + kk];
        }
        #pragma unroll
        for (int i = 0; i < 4; i++) {
            int e = tid + i*256;
            int kk = e >> 6, n = e & 63;
            Ws[kk][n] = W[(size_t)(k0+kk)*N + n0 + n];
        }
        __syncthreads();
        #pragma unroll
        for (int kk = 0; kk < 16; kk++) {
            float a[4], w[4];
            #pragma unroll
            for (int i = 0; i < 4; i++) a[i] = As[kk][ty*4+i];
            #pragma unroll
            for (int j = 0; j < 4; j++) w[j] = Ws[kk][tx*4+j];
            #pragma unroll
            for (int i = 0; i < 4; i++)
                #pragma unroll
                for (int j = 0; j < 4; j++)
                    acc[i][j] += a[i] * w[j];
        }
        __syncthreads();
    }
    #pragma unroll
    for (int i = 0; i < 4; i++) {
        int m = m0 + ty*4 + i;
        #pragma unroll
        for (int j = 0; j < 4; j++) {
            int n = n0 + tx*4 + j;
            C[(size_t)m*N + n] = acc[i][j] + bias[n];
        }
    }
}

// ---------------- 3. per-token feature scalars (one warp per (b,h,t)) ----------------
__global__ void token_kernel(const float* __restrict__ Wta, const float* __restrict__ bta,
                             const float* __restrict__ Wtb, const float* __restrict__ btb) {
    int gw   = (blockIdx.x * blockDim.x + threadIdx.x) >> 5;
    int lane = threadIdx.x & 31;
    if (gw >= NBHT) return;
    int bh = gw >> 10, t = gw & 1023;
    int b = bh >> 3, h = bh & 7;
    size_t base = ((size_t)(b*Tt + t))*DM + h*DEP;
    float q0 = g_Q[base+lane], q1 = g_Q[base+lane+32];
    float k0 = g_K[base+lane], k1 = g_K[base+lane+32];

    float sphiq = q0*g_wphi[lane]    + q1*g_wphi[lane+32];
    float sphik = k0*g_wphi[64+lane] + k1*g_wphi[96+lane];
    float staq  = q0*Wta[lane]       + q1*Wta[lane+32];
    float stak  = k0*Wta[64+lane]    + k1*Wta[96+lane];
    float stbq  = q0*Wtb[lane]       + q1*Wtb[lane+32];
    float stbk  = k0*Wtb[64+lane]    + k1*Wtb[96+lane];
    float stauq = q0*g_wtau[lane]    + q1*g_wtau[lane+32];
    float stauk = k0*g_wtau[64+lane] + k1*g_wtau[96+lane];

    #pragma unroll
    for (int off = 16; off; off >>= 1) {
        sphiq += __shfl_xor_sync(0xffffffffu, sphiq, off);
        sphik += __shfl_xor_sync(0xffffffffu, sphik, off);
        staq  += __shfl_xor_sync(0xffffffffu, staq,  off);
        stak  += __shfl_xor_sync(0xffffffffu, stak,  off);
        stbq  += __shfl_xor_sync(0xffffffffu, stbq,  off);
        stbk  += __shfl_xor_sync(0xffffffffu, stbk,  off);
        stauq += __shfl_xor_sync(0xffffffffu, stauq, off);
        stauk += __shfl_xor_sync(0xffffffffu, stauk, off);
    }
    if (lane == 0) {
        g_pq_phi[gw] = sphiq + g_cphi[0];
        g_pk_phi[gw] = sphik;
        g_pq_ta [gw] = staq + bta[0];
        g_pk_ta [gw] = stak;
        g_pq_tb [gw] = stbq + btb[0];
        g_pk_tb [gw] = stbk;
        g_pq_tau[gw] = stauq + g_ctau[0];
        g_pk_tau[gw] = stauk;
    }
}

// ---------------- 4. scores S[bh,q,j] = q_h . k_h (NT GEMM, full d=64 resident) ----------------
__global__ void scores_kernel() {
    __shared__ float Qs[64][65];  // [d][q]
    __shared__ float Ks[64][65];  // [d][j]
    const int tid = threadIdx.x;
    const int tx = tid & 15, ty = tid >> 4;
    const int bh = blockIdx.z;
    const int b = bh >> 3, h = bh & 7;
    const int q0 = blockIdx.y * 64, j0 = blockIdx.x * 64;
    #pragma unroll
    for (int i = 0; i < 16; i++) {
        int e = tid + i*256;       // 0..4095
        int r = e >> 6, d = e & 63;
        Qs[d][r] = g_Q[((size_t)(b*Tt + q0 + r))*DM + h*DEP + d];
        Ks[d][r] = g_K[((size_t)(b*Tt + j0 + r))*DM + h*DEP + d];
    }
    __syncthreads();
    float acc[4][4] = {};
    #pragma unroll
    for (int d = 0; d < 64; d++) {
        float a[4], w[4];
        #pragma unroll
        for (int i = 0; i < 4; i++) a[i] = Qs[d][ty*4+i];
        #pragma unroll
        for (int j = 0; j < 4; j++) w[j] = Ks[d][tx*4+j];
        #pragma unroll
        for (int i = 0; i < 4; i++)
            #pragma unroll
            for (int j = 0; j < 4; j++)
                acc[i][j] += a[i] * w[j];
    }
    #pragma unroll
    for (int i = 0; i < 4; i++)
        #pragma unroll
        for (int j = 0; j < 4; j++)
            g_S[((size_t)bh*Tt + q0 + ty*4 + i)*Tt + j0 + tx*4 + j] = acc[i][j];
}

// ---------------- 5. fused top-16 + logits + softmax + V-gather (warp per query) ----------------
__global__ void attn_kernel() {
    __shared__ float sc[8][1024];
    const unsigned FULL = 0xffffffffu;
    int warp = threadIdx.x >> 5, lane = threadIdx.x & 31;
    int wq = blockIdx.x * 8 + warp;
    int bh = wq >> 10, q = wq & 1023;
    int b = bh >> 3, h = bh & 7;

    const float* srow = g_S + ((size_t)bh*Tt + q)*Tt;
    float* s = sc[warp];
    for (int i = lane; i < 1024; i += 32) s[i] = srow[i];
    __syncwarp();

    int jsel = 0;
    for (int r = 0; r < 16; r++) {
        float best = -INFINITY; int bi = 0;
        #pragma unroll
        for (int u = 0; u < 32; u++) {
            int i = lane + u*32;
            float v = s[i];
            if (v > best) { best = v; bi = i; }   // strict > : lowest index wins per lane
        }
        #pragma unroll
        for (int off = 16; off; off >>= 1) {
            float ov = __shfl_xor_sync(FULL, best, off);
            int   oi = __shfl_xor_sync(FULL, bi,   off);
            if (ov > best || (ov == best && oi < bi)) { best = ov; bi = oi; }
        }
        if (lane == r) jsel = bi;
        if ((bi & 31) == lane) s[bi] = -INFINITY;
        __syncwarp();
    }

    // logits for the 16 selected keys (lanes 0..15)
    float logit = -INFINITY;
    int pqi = bh*1024 + q;
    if (lane < 16) {
        int pki = bh*1024 + jsel;
        float aphi = g_pq_phi[pqi] + g_pk_phi[pki];
        float phi  = 1.f / (1.f + expf(-aphi));
        float ta   = g_pq_ta[pqi]  + g_pk_ta[pki];
        float tb   = g_pq_tb[pqi]  + g_pk_tb[pki];
        float ti   = 1.f / (1.f + expf(-(ta + tb)));      // t_scalar = 1
        float xt   = g_pq_tau[pqi] + g_pk_tau[pki];
        float sp   = (xt > 20.f) ? xt : log1pf(expf(xt)); // softplus
        float tau  = sp + 1e-6f;
        logit = phi / tau * (1.f - expf(-tau * ti));
    }
    // softmax over the 16 active lanes (others hold -inf / 0)
    float m = logit;
    #pragma unroll
    for (int off = 16; off; off >>= 1) m = fmaxf(m, __shfl_xor_sync(FULL, m, off));
    float e = (lane < 16) ? expf(logit - m) : 0.f;
    float ssum = e;
    #pragma unroll
    for (int off = 16; off; off >>= 1) ssum += __shfl_xor_sync(FULL, ssum, off);
    float aw = e / ssum;

    // out[d] = sum_l attn_l * V[j_l][d]  (d split: lane, lane+32)
    float acc0 = 0.f, acc1 = 0.f;
    #pragma unroll
    for (int l = 0; l < 16; l++) {
        float a = __shfl_sync(FULL, aw,   l);
        int   j = __shfl_sync(FULL, jsel, l);
        const float* vp = g_V + ((size_t)(b*Tt + j))*DM + h*DEP;
        acc0 += a * vp[lane];
        acc1 += a * vp[lane+32];
    }
    float* op = g_Cb + ((size_t)(b*Tt + q))*DM + h*DEP;
    op[lane]    = acc0;   // DT = 1
    op[lane+32] = acc1;
}

// ---------------- launch ----------------
extern "C" void kernel_launch(void* const* d_in, const int* in_sizes, int n_in,
                              void* d_out, int out_size) {
    const float* x   = (const float*)d_in[0];
    const float* Wq  = (const float*)d_in[1];
    const float* bq  = (const float*)d_in[2];
    const float* Wk  = (const float*)d_in[3];
    const float* bk  = (const float*)d_in[4];
    const float* Wv  = (const float*)d_in[5];
    const float* bv  = (const float*)d_in[6];
    const float* Wo  = (const float*)d_in[7];
    const float* bo  = (const float*)d_in[8];
    const float* Wpi = (const float*)d_in[9];
    const float* bpi = (const float*)d_in[10];
    const float* Wpo = (const float*)d_in[11];
    const float* bpo = (const float*)d_in[12];
    const float* Wta = (const float*)d_in[13];
    const float* bta = (const float*)d_in[14];
    const float* Wtb = (const float*)d_in[15];
    const float* btb = (const float*)d_in[16];
    const float* Wti = (const float*)d_in[17];
    const float* bti = (const float*)d_in[18];
    const float* Wto = (const float*)d_in[19];
    const float* bto = (const float*)d_in[20];

    float *Qp, *Kp, *Vp, *Cbp;
    cudaGetSymbolAddress((void**)&Qp,  g_Q);
    cudaGetSymbolAddress((void**)&Kp,  g_K);
    cudaGetSymbolAddress((void**)&Vp,  g_V);
    cudaGetSymbolAddress((void**)&Cbp, g_Cb);

    combine_kernel<<<1, 128>>>(Wpi, bpi, Wpo, bpo, Wti, bti, Wto, bto);

    dim3 gg(512/64, 2048/64);   // (8, 32)
    gemm_bias<<<gg, 256>>>(x, Wq, bq, Qp, 2048, 512, 512);
    gemm_bias<<<gg, 256>>>(x, Wk, bk, Kp, 2048, 512, 512);
    gemm_bias<<<gg, 256>>>(x, Wv, bv, Vp, 2048, 512, 512);

    token_kernel<<<NBHT/8, 256>>>(Wta, bta, Wtb, btb);

    scores_kernel<<<dim3(16, 16, 16), 256>>>();

    attn_kernel<<<NBHT/8, 256>>>();

    gemm_bias<<<gg, 256>>>(Cbp, Wo, bo, (float*)d_out, 2048, 512, 512);
}

// round 2
// speedup vs baseline: 1.1562x; 1.1562x over previous
#include <cuda_runtime.h>
#include <math.h>

#define Bq 2
#define Tt 1024
#define DM 512
#define Hh 8
#define DEP 64
#define NTOK (Bq*Tt)      // 2048
#define BH   (Bq*Hh)      // 16
#define NBHT (BH*Tt)      // 16384

// ---------------- scratch (device globals; no allocation) ----------------
__device__ float g_Q[NTOK*DM];
__device__ float g_K[NTOK*DM];
__device__ float g_V[NTOK*DM];
__device__ float g_Cb[NTOK*DM];
__device__ float g_S[(size_t)BH*Tt*Tt];   // 64 MB scores
__device__ float g_wphi[128];
__device__ float g_wtau[128];
__device__ float g_cphi[1];
__device__ float g_ctau[1];
__device__ float g_pq_phi[NBHT], g_pk_phi[NBHT];
__device__ float g_pq_ta [NBHT], g_pk_ta [NBHT];
__device__ float g_pq_tb [NBHT], g_pk_tb [NBHT];
__device__ float g_pq_tau[NBHT], g_pk_tau[NBHT];

// ---------------- 1. collapse the linear-linear per-pair MLPs ----------------
__global__ void combine_kernel(const float* __restrict__ Wpi, const float* __restrict__ bpi,
                               const float* __restrict__ Wpo, const float* __restrict__ bpo,
                               const float* __restrict__ Wti, const float* __restrict__ bti,
                               const float* __restrict__ Wto, const float* __restrict__ bto) {
    int i = threadIdx.x;  // 128 threads
    float s = 0.f;
    for (int m = 0; m < 512; m++) s += Wpi[i*512 + m] * Wpo[m];
    g_wphi[i] = s;
    float s2 = 0.f;
    for (int m = 0; m < 256; m++) s2 += Wti[i*256 + m] * Wto[m];
    g_wtau[i] = s2;
    if (i == 0) {
        float c = bpo[0];
        for (int m = 0; m < 512; m++) c += bpi[m] * Wpo[m];
        g_cphi[0] = c;
        float c2 = bto[0];
        for (int m = 0; m < 256; m++) c2 += bti[m] * Wto[m];
        g_ctau[0] = c2;
    }
}

// ---------------- 2. GEMM: C[2048,512] = A[2048,512] @ W[512,512] + bias ----------------
// 128x64 tile, BK=16, 256 threads, 8x4 per thread. Optional z-mux over 3 weight sets.
__global__ void __launch_bounds__(256, 3)
gemm_bias3(const float* __restrict__ A,
           const float* __restrict__ W0, const float* __restrict__ b0, float* __restrict__ C0,
           const float* __restrict__ W1, const float* __restrict__ b1, float* __restrict__ C1,
           const float* __restrict__ W2, const float* __restrict__ b2, float* __restrict__ C2) {
    __shared__ float As[16][132];   // [k][m], 132 = 4*33 keeps float4 alignment
    __shared__ float Ws[16][68];    // [k][n]
    const int tid = threadIdx.x;
    const int tx = tid & 15, ty = tid >> 4;     // tx->n (4 cols), ty->m (8 rows)
    const int m0 = blockIdx.y * 128, n0 = blockIdx.x * 64;
    const int z = blockIdx.z;
    const float* W  = (z == 0) ? W0 : (z == 1) ? W1 : W2;
    const float* bi = (z == 0) ? b0 : (z == 1) ? b1 : b2;
    float*       C  = (z == 0) ? C0 : (z == 1) ? C1 : C2;

    const int ar   = tid >> 1;        // 0..127 row for A loads
    const int ah   = (tid & 1) * 8;   // k-half
    const int wkk  = tid >> 4;        // 0..15 k for W loads
    const int wn   = (tid & 15) * 4;  // n offset

    float acc[8][4] = {};
    for (int k0 = 0; k0 < 512; k0 += 16) {
        // A tile: 128 rows x 16 k
        const float* ap = A + (size_t)(m0 + ar) * 512 + k0 + ah;
        float4 a0 = *(const float4*)(ap);
        float4 a1 = *(const float4*)(ap + 4);
        As[ah + 0][ar] = a0.x; As[ah + 1][ar] = a0.y;
        As[ah + 2][ar] = a0.z; As[ah + 3][ar] = a0.w;
        As[ah + 4][ar] = a1.x; As[ah + 5][ar] = a1.y;
        As[ah + 6][ar] = a1.z; As[ah + 7][ar] = a1.w;
        // W tile: 16 k x 64 n
        *(float4*)&Ws[wkk][wn] = *(const float4*)(W + (size_t)(k0 + wkk) * 512 + n0 + wn);
        __syncthreads();
        #pragma unroll
        for (int kk = 0; kk < 16; kk++) {
            float a[8], w[4];
            *(float4*)(a)     = *(float4*)&As[kk][ty*8];
            *(float4*)(a + 4) = *(float4*)&As[kk][ty*8 + 4];
            *(float4*)(w)     = *(float4*)&Ws[kk][tx*4];
            #pragma unroll
            for (int i = 0; i < 8; i++)
                #pragma unroll
                for (int j = 0; j < 4; j++)
                    acc[i][j] += a[i] * w[j];
        }
        __syncthreads();
    }
    float4 bv = *(const float4*)(bi + n0 + tx*4);
    #pragma unroll
    for (int i = 0; i < 8; i++) {
        float4 o;
        o.x = acc[i][0] + bv.x; o.y = acc[i][1] + bv.y;
        o.z = acc[i][2] + bv.z; o.w = acc[i][3] + bv.w;
        *(float4*)(C + (size_t)(m0 + ty*8 + i) * 512 + n0 + tx*4) = o;
    }
}

// ---------------- 3. per-token feature scalars (one warp per (b,h,t)) ----------------
__global__ void token_kernel(const float* __restrict__ Wta, const float* __restrict__ bta,
                             const float* __restrict__ Wtb, const float* __restrict__ btb) {
    int gw   = (blockIdx.x * blockDim.x + threadIdx.x) >> 5;
    int lane = threadIdx.x & 31;
    if (gw >= NBHT) return;
    int bh = gw >> 10, t = gw & 1023;
    int b = bh >> 3, h = bh & 7;
    size_t base = ((size_t)(b*Tt + t))*DM + h*DEP;
    float q0 = g_Q[base+lane], q1 = g_Q[base+lane+32];
    float k0 = g_K[base+lane], k1 = g_K[base+lane+32];

    float sphiq = q0*g_wphi[lane]    + q1*g_wphi[lane+32];
    float sphik = k0*g_wphi[64+lane] + k1*g_wphi[96+lane];
    float staq  = q0*Wta[lane]       + q1*Wta[lane+32];
    float stak  = k0*Wta[64+lane]    + k1*Wta[96+lane];
    float stbq  = q0*Wtb[lane]       + q1*Wtb[lane+32];
    float stbk  = k0*Wtb[64+lane]    + k1*Wtb[96+lane];
    float stauq = q0*g_wtau[lane]    + q1*g_wtau[lane+32];
    float stauk = k0*g_wtau[64+lane] + k1*g_wtau[96+lane];

    #pragma unroll
    for (int off = 16; off; off >>= 1) {
        sphiq += __shfl_xor_sync(0xffffffffu, sphiq, off);
        sphik += __shfl_xor_sync(0xffffffffu, sphik, off);
        staq  += __shfl_xor_sync(0xffffffffu, staq,  off);
        stak  += __shfl_xor_sync(0xffffffffu, stak,  off);
        stbq  += __shfl_xor_sync(0xffffffffu, stbq,  off);
        stbk  += __shfl_xor_sync(0xffffffffu, stbk,  off);
        stauq += __shfl_xor_sync(0xffffffffu, stauq, off);
        stauk += __shfl_xor_sync(0xffffffffu, stauk, off);
    }
    if (lane == 0) {
        g_pq_phi[gw] = sphiq + g_cphi[0];
        g_pk_phi[gw] = sphik;
        g_pq_ta [gw] = staq + bta[0];
        g_pk_ta [gw] = stak;
        g_pq_tb [gw] = stbq + btb[0];
        g_pk_tb [gw] = stbk;
        g_pq_tau[gw] = stauq + g_ctau[0];
        g_pk_tau[gw] = stauk;
    }
}

// ---------------- 4. scores S[bh,q,j] = q_h . k_h  (128x128 tile, 8x8/thread) ----------------
__global__ void __launch_bounds__(256, 2) scores_kernel() {
    __shared__ float Qs[32][132];   // [d][q-row]
    __shared__ float Ks[32][132];   // [d][j-row]
    const int tid = threadIdx.x;
    const int tx = tid & 15, ty = tid >> 4;
    const int bh = blockIdx.z;
    const int b = bh >> 3, h = bh & 7;
    const int j0 = blockIdx.x * 128, q0 = blockIdx.y * 128;
    const int r = tid >> 1, half = (tid & 1) * 16;

    float acc[8][8] = {};
    #pragma unroll
    for (int c = 0; c < 2; c++) {
        const int d0 = c * 32;
        const float* qp = g_Q + ((size_t)(b*Tt + q0 + r))*DM + h*DEP + d0 + half;
        const float* kp = g_K + ((size_t)(b*Tt + j0 + r))*DM + h*DEP + d0 + half;
        #pragma unroll
        for (int u = 0; u < 4; u++) {
            float4 qv = *(const float4*)(qp + u*4);
            float4 kv = *(const float4*)(kp + u*4);
            int d = half + u*4;
            Qs[d+0][r] = qv.x; Qs[d+1][r] = qv.y; Qs[d+2][r] = qv.z; Qs[d+3][r] = qv.w;
            Ks[d+0][r] = kv.x; Ks[d+1][r] = kv.y; Ks[d+2][r] = kv.z; Ks[d+3][r] = kv.w;
        }
        __syncthreads();
        #pragma unroll
        for (int d = 0; d < 32; d++) {
            float a[8], w[8];
            *(float4*)(a)     = *(float4*)&Qs[d][ty*8];
            *(float4*)(a + 4) = *(float4*)&Qs[d][ty*8 + 4];
            *(float4*)(w)     = *(float4*)&Ks[d][tx*8];
            *(float4*)(w + 4) = *(float4*)&Ks[d][tx*8 + 4];
            #pragma unroll
            for (int i = 0; i < 8; i++)
                #pragma unroll
                for (int j = 0; j < 8; j++)
                    acc[i][j] += a[i] * w[j];
        }
        __syncthreads();
    }
    #pragma unroll
    for (int i = 0; i < 8; i++) {
        float* out = g_S + ((size_t)bh*Tt + q0 + ty*8 + i)*Tt + j0 + tx*8;
        *(float4*)(out)     = make_float4(acc[i][0], acc[i][1], acc[i][2], acc[i][3]);
        *(float4*)(out + 4) = make_float4(acc[i][4], acc[i][5], acc[i][6], acc[i][7]);
    }
}

// ---------------- 5. fused top-16 + logits + softmax + V-gather (warp per query) ----------------
__global__ void attn_kernel() {
    __shared__ float sc[8][1024];
    const unsigned FULL = 0xffffffffu;
    int warp = threadIdx.x >> 5, lane = threadIdx.x & 31;
    int wq = blockIdx.x * 8 + warp;
    int bh = wq >> 10, q = wq & 1023;
    int b = bh >> 3, h = bh & 7;

    const float* srow = g_S + ((size_t)bh*Tt + q)*Tt;
    float* s = sc[warp];
    for (int i = lane; i < 1024; i += 32) s[i] = srow[i];
    __syncwarp();

    int jsel = 0;
    for (int r = 0; r < 16; r++) {
        float best = -INFINITY; int bi = 0;
        #pragma unroll
        for (int u = 0; u < 32; u++) {
            int i = lane + u*32;
            float v = s[i];
            if (v > best) { best = v; bi = i; }   // strict > : lowest index wins per lane
        }
        #pragma unroll
        for (int off = 16; off; off >>= 1) {
            float ov = __shfl_xor_sync(FULL, best, off);
            int   oi = __shfl_xor_sync(FULL, bi,   off);
            if (ov > best || (ov == best && oi < bi)) { best = ov; bi = oi; }
        }
        if (lane == r) jsel = bi;
        if ((bi & 31) == lane) s[bi] = -INFINITY;
        __syncwarp();
    }

    // logits for the 16 selected keys (lanes 0..15)
    float logit = -INFINITY;
    int pqi = bh*1024 + q;
    if (lane < 16) {
        int pki = bh*1024 + jsel;
        float aphi = g_pq_phi[pqi] + g_pk_phi[pki];
        float phi  = 1.f / (1.f + expf(-aphi));
        float ta   = g_pq_ta[pqi]  + g_pk_ta[pki];
        float tb   = g_pq_tb[pqi]  + g_pk_tb[pki];
        float ti   = 1.f / (1.f + expf(-(ta + tb)));      // t_scalar = 1
        float xt   = g_pq_tau[pqi] + g_pk_tau[pki];
        float sp   = (xt > 20.f) ? xt : log1pf(expf(xt)); // softplus
        float tau  = sp + 1e-6f;
        logit = phi / tau * (1.f - expf(-tau * ti));
    }
    // softmax over the 16 active lanes (others hold -inf / 0)
    float m = logit;
    #pragma unroll
    for (int off = 16; off; off >>= 1) m = fmaxf(m, __shfl_xor_sync(FULL, m, off));
    float e = (lane < 16) ? expf(logit - m) : 0.f;
    float ssum = e;
    #pragma unroll
    for (int off = 16; off; off >>= 1) ssum += __shfl_xor_sync(FULL, ssum, off);
    float aw = e / ssum;

    // out[d] = sum_l attn_l * V[j_l][d]  (d split: lane, lane+32)
    float acc0 = 0.f, acc1 = 0.f;
    #pragma unroll
    for (int l = 0; l < 16; l++) {
        float a = __shfl_sync(FULL, aw,   l);
        int   j = __shfl_sync(FULL, jsel, l);
        const float* vp = g_V + ((size_t)(b*Tt + j))*DM + h*DEP;
        acc0 += a * vp[lane];
        acc1 += a * vp[lane+32];
    }
    float* op = g_Cb + ((size_t)(b*Tt + q))*DM + h*DEP;
    op[lane]    = acc0;   // DT = 1
    op[lane+32] = acc1;
}

// ---------------- launch ----------------
extern "C" void kernel_launch(void* const* d_in, const int* in_sizes, int n_in,
                              void* d_out, int out_size) {
    const float* x   = (const float*)d_in[0];
    const float* Wq  = (const float*)d_in[1];
    const float* bq  = (const float*)d_in[2];
    const float* Wk  = (const float*)d_in[3];
    const float* bk  = (const float*)d_in[4];
    const float* Wv  = (const float*)d_in[5];
    const float* bv  = (const float*)d_in[6];
    const float* Wo  = (const float*)d_in[7];
    const float* bo  = (const float*)d_in[8];
    const float* Wpi = (const float*)d_in[9];
    const float* bpi = (const float*)d_in[10];
    const float* Wpo = (const float*)d_in[11];
    const float* bpo = (const float*)d_in[12];
    const float* Wta = (const float*)d_in[13];
    const float* bta = (const float*)d_in[14];
    const float* Wtb = (const float*)d_in[15];
    const float* btb = (const float*)d_in[16];
    const float* Wti = (const float*)d_in[17];
    const float* bti = (const float*)d_in[18];
    const float* Wto = (const float*)d_in[19];
    const float* bto = (const float*)d_in[20];

    float *Qp, *Kp, *Vp, *Cbp;
    cudaGetSymbolAddress((void**)&Qp,  g_Q);
    cudaGetSymbolAddress((void**)&Kp,  g_K);
    cudaGetSymbolAddress((void**)&Vp,  g_V);
    cudaGetSymbolAddress((void**)&Cbp, g_Cb);

    combine_kernel<<<1, 128>>>(Wpi, bpi, Wpo, bpo, Wti, bti, Wto, bto);

    // fused Q/K/V: 128x64 tiles -> grid (8, 16, 3)
    gemm_bias3<<<dim3(8, 16, 3), 256>>>(x, Wq, bq, Qp, Wk, bk, Kp, Wv, bv, Vp);

    token_kernel<<<NBHT/8, 256>>>(Wta, bta, Wtb, btb);

    scores_kernel<<<dim3(8, 8, 16), 256>>>();

    attn_kernel<<<NBHT/8, 256>>>();

    // output GEMM reuses the same kernel (z = 0 only)
    gemm_bias3<<<dim3(8, 16, 1), 256>>>(Cbp, Wo, bo, (float*)d_out,
                                        Wo, bo, (float*)d_out, Wo, bo, (float*)d_out);
}